// round 2
// baseline (speedup 1.0000x reference)
#include <cuda_runtime.h>

#define B_ 16
#define N_ 2048
#define D_ 256
#define H_ 64
#define TM 14          // output rows per tile
#define SROWS 16       // TM + 2 halo rows
#define NTILES 147     // ceil(N_/TM)
#define KTS 260        // padded stride for transposed k chunk (multiple of 4, 260%32==4)
#define SCALE 0.125f   // H^-0.5

__device__ float g_q[B_*N_*H_];
__device__ float g_k[B_*N_*H_];
__device__ float g_v[B_*N_*H_];

// ---------------------------------------------------------------------------
// Kernel 1: QKV projection.  out[b,n,h] = x[b,n,:] @ W[:,h] + bias[h]
// grid = (512, 3): 64 rows per CTA, blockIdx.y selects {q,k,v}
// ---------------------------------------------------------------------------
__global__ __launch_bounds__(256) void qkv_kernel_75625784(
    const float* __restrict__ x,
    const float* __restrict__ Wq, const float* __restrict__ bq,
    const float* __restrict__ Wk, const float* __restrict__ bk,
    const float* __restrict__ Wv, const float* __restrict__ bv)
{
    __shared__ float xs[64*64];
    __shared__ float ws[64*64];
    const int mat = blockIdx.y;
    const float* W    = (mat==0) ? Wq : (mat==1 ? Wk : Wv);
    const float* bias = (mat==0) ? bq : (mat==1 ? bk : bv);
    float* outg       = (mat==0) ? g_q : (mat==1 ? g_k : g_v);
    const int row0 = blockIdx.x * 64;
    const int tid = threadIdx.x;
    const int rt = tid >> 4;    // 0..15  (rows rt*4..rt*4+3)
    const int ht = tid & 15;    // 0..15  (cols ht*4..ht*4+3)

    float acc[4][4];
    #pragma unroll
    for (int i = 0; i < 4; ++i)
        #pragma unroll
        for (int j = 0; j < 4; ++j) acc[i][j] = 0.f;

    for (int dc = 0; dc < D_; dc += 64) {
        #pragma unroll
        for (int it = 0; it < 4; ++it) {
            int fi = it*256 + tid;
            int r = fi >> 4, c4 = fi & 15;
            *(float4*)&xs[r*64 + c4*4] =
                *(const float4*)&x[(size_t)(row0 + r)*D_ + dc + c4*4];
            *(float4*)&ws[r*64 + c4*4] =
                *(const float4*)&W[(size_t)(dc + r)*H_ + c4*4];
        }
        __syncthreads();
        #pragma unroll
        for (int d4 = 0; d4 < 16; ++d4) {
            float av[4][4], bv4[4][4];
            #pragma unroll
            for (int i = 0; i < 4; ++i) {
                float4 t = *(const float4*)&xs[(rt*4+i)*64 + d4*4];
                av[i][0]=t.x; av[i][1]=t.y; av[i][2]=t.z; av[i][3]=t.w;
            }
            #pragma unroll
            for (int u = 0; u < 4; ++u) {
                float4 t = *(const float4*)&ws[(d4*4+u)*64 + ht*4];
                bv4[u][0]=t.x; bv4[u][1]=t.y; bv4[u][2]=t.z; bv4[u][3]=t.w;
            }
            #pragma unroll
            for (int i = 0; i < 4; ++i)
                #pragma unroll
                for (int j = 0; j < 4; ++j)
                    acc[i][j] += av[i][0]*bv4[0][j] + av[i][1]*bv4[1][j]
                               + av[i][2]*bv4[2][j] + av[i][3]*bv4[3][j];
        }
        __syncthreads();
    }
    float4 bb = *(const float4*)&bias[ht*4];
    #pragma unroll
    for (int i = 0; i < 4; ++i) {
        float4 r;
        r.x = acc[i][0] + bb.x; r.y = acc[i][1] + bb.y;
        r.z = acc[i][2] + bb.z; r.w = acc[i][3] + bb.w;
        *(float4*)&outg[(size_t)(row0 + rt*4 + i)*H_ + ht*4] = r;
    }
}

// ---------------------------------------------------------------------------
// Kernel 2: fused  A = scale*(q k^T); conv3x3+sigmoid; relu(A - .); expm1;
//           zero-softmax-normalized e @ v.
// grid = (NTILES, B_), 256 threads, ~202 KB dynamic smem (1 CTA/SM)
// ---------------------------------------------------------------------------
__global__ __launch_bounds__(256, 1) void attn_kernel_75625784(
    const float* __restrict__ conv_w, const float* __restrict__ conv_b,
    float* __restrict__ out)
{
    extern __shared__ float smem[];
    float* s      = smem;                      // [SROWS][N_]      131072 B
    float* kt     = s + SROWS*N_;              // [64][KTS]         66560 B (reused: vt[128][64], scratch[4][16][64])
    float* qt     = kt + 64*KTS;               // [SROWS][H_]        4096 B
    float* rowsum = qt + SROWS*H_;             // [16]
    float* cw     = rowsum + 16;               // [10]

    const int b   = blockIdx.y;
    const int r0  = blockIdx.x * TM;
    const int tid = threadIdx.x;

    if (tid < 16) rowsum[tid] = 0.f;
    if (tid < 9)  cw[tid] = conv_w[tid];
    if (tid == 9) cw[9]   = conv_b[0];
    // q tile (16 rows incl. halo; out-of-range rows zeroed => s row == 0, matching conv zero-pad)
    {
        int i = tid >> 4, h4 = tid & 15;
        int g = r0 - 1 + i;
        float4 qv = make_float4(0.f, 0.f, 0.f, 0.f);
        if (g >= 0 && g < N_)
            qv = *(const float4*)&g_q[((size_t)b*N_ + g)*H_ + h4*4];
        *(float4*)&qt[i*H_ + h4*4] = qv;
    }
    __syncthreads();

    // ---------------- Phase 1: s[i][m] = scale * q_i . k_m ----------------
    {
        const int rt = tid >> 6;          // 0..3  -> rows rt*4..rt*4+3
        const int ct = tid & 63;          // 0..63 -> cols ct*4..ct*4+3 within chunk
        const int hh = tid & 63;          // transpose-loader role
        const int mg = tid >> 6;

        for (int mb = 0; mb < N_; mb += 256) {
            const float* kbase = &g_k[((size_t)b*N_ + mb)*H_];
            #pragma unroll
            for (int it = 0; it < 16; ++it) {
                int m0 = mg*4 + it*16;
                float4 v;
                v.x = kbase[(m0+0)*H_ + hh];
                v.y = kbase[(m0+1)*H_ + hh];
                v.z = kbase[(m0+2)*H_ + hh];
                v.w = kbase[(m0+3)*H_ + hh];
                *(float4*)&kt[hh*KTS + m0] = v;     // conflict-free (stride 260)
            }
            __syncthreads();

            float acc[4][4];
            #pragma unroll
            for (int i = 0; i < 4; ++i)
                #pragma unroll
                for (int j = 0; j < 4; ++j) acc[i][j] = 0.f;

            #pragma unroll
            for (int k4 = 0; k4 < 16; ++k4) {
                float av[4][4], bv4[4][4];
                #pragma unroll
                for (int i = 0; i < 4; ++i) {
                    float4 t = *(const float4*)&qt[(rt*4+i)*H_ + k4*4];
                    av[i][0]=t.x; av[i][1]=t.y; av[i][2]=t.z; av[i][3]=t.w;
                }
                #pragma unroll
                for (int u = 0; u < 4; ++u) {
                    float4 t = *(const float4*)&kt[(k4*4+u)*KTS + ct*4];
                    bv4[u][0]=t.x; bv4[u][1]=t.y; bv4[u][2]=t.z; bv4[u][3]=t.w;
                }
                #pragma unroll
                for (int i = 0; i < 4; ++i)
                    #pragma unroll
                    for (int j = 0; j < 4; ++j)
                        acc[i][j] += av[i][0]*bv4[0][j] + av[i][1]*bv4[1][j]
                                   + av[i][2]*bv4[2][j] + av[i][3]*bv4[3][j];
            }
            #pragma unroll
            for (int i = 0; i < 4; ++i) {
                float4 r;
                r.x = acc[i][0]*SCALE; r.y = acc[i][1]*SCALE;
                r.z = acc[i][2]*SCALE; r.w = acc[i][3]*SCALE;
                *(float4*)&s[(rt*4+i)*N_ + mb + ct*4] = r;
            }
            __syncthreads();
        }
    }

    // ------- Phase 2: conv3x3 + sigmoid + relu + (exp-1), in-place shift -------
    {
        const float w0=cw[0],w1=cw[1],w2=cw[2],w3=cw[3],w4=cw[4],
                    w5=cw[5],w6=cw[6],w7=cw[7],w8=cw[8],cb=cw[9];
        const int lane = tid & 31;
        for (int i = 1; i <= TM; ++i) {
            float ev[8]; float psum = 0.f;
            const float* sm1 = &s[(i-1)*N_];
            const float* s0  = &s[ i   *N_];
            const float* sp1 = &s[(i+1)*N_];
            #pragma unroll
            for (int j = 0; j < 8; ++j) {
                int m = tid + j*256;
                float l0 = (m>0)     ? sm1[m-1] : 0.f;
                float l1 = sm1[m];
                float l2 = (m<N_-1)  ? sm1[m+1] : 0.f;
                float c0 = (m>0)     ? s0[m-1]  : 0.f;
                float c1 = s0[m];
                float c2 = (m<N_-1)  ? s0[m+1]  : 0.f;
                float d0 = (m>0)     ? sp1[m-1] : 0.f;
                float d1 = sp1[m];
                float d2 = (m<N_-1)  ? sp1[m+1] : 0.f;
                float conv = cb + w0*l0 + w1*l1 + w2*l2
                                + w3*c0 + w4*c1 + w5*c2
                                + w6*d0 + w7*d1 + w8*d2;
                float sig = __fdividef(1.f, 1.f + __expf(-conv));
                float a = c1 - sig;
                a = fmaxf(a, 0.f);
                float e = __expf(a) - 1.f;
                ev[j] = e; psum += e;
            }
            __syncthreads();                    // all reads of row i-1 done
            #pragma unroll
            for (int j = 0; j < 8; ++j) s[(i-1)*N_ + tid + j*256] = ev[j];
            #pragma unroll
            for (int off = 16; off > 0; off >>= 1)
                psum += __shfl_down_sync(0xffffffffu, psum, off);
            if (lane == 0) atomicAdd(&rowsum[i-1], psum);
            __syncthreads();
        }
        // rows TM..SROWS-1 are stale A_dense halo -> zero so phase 3 tiles cleanly
        for (int idx = tid; idx < 2*N_; idx += 256) s[TM*N_ + idx] = 0.f;
        __syncthreads();
    }

    // ---------------- Phase 3: out = (e @ v) / (rowsum + eps) ----------------
    {
        const int mt = tid >> 6;          // m-quarter 0..3
        const int rt = (tid >> 4) & 3;    // rows rt*4..rt*4+3
        const int ht = tid & 15;          // h cols ht*4..ht*4+3
        float acc[4][4];
        #pragma unroll
        for (int i = 0; i < 4; ++i)
            #pragma unroll
            for (int j = 0; j < 4; ++j) acc[i][j] = 0.f;

        float* vt = kt;                   // reuse as [128][64]
        for (int stp = 0; stp < 16; ++stp) {
            #pragma unroll
            for (int it = 0; it < 8; ++it) {
                int fi = it*256 + tid;           // 0..2047 float4 slots
                int g = fi >> 9, rem = fi & 511;
                int mi = rem >> 4, h4 = rem & 15;
                int m = g*512 + stp*32 + mi;
                *(float4*)&vt[(g*32+mi)*64 + h4*4] =
                    *(const float4*)&g_v[((size_t)b*N_ + m)*H_ + h4*4];
            }
            __syncthreads();
            const int mloc = mt*32;
            const int mgs  = mt*512 + stp*32;
            #pragma unroll
            for (int mi = 0; mi < 32; mi += 4) {
                float ev[4][4], vv[4][4];
                #pragma unroll
                for (int i = 0; i < 4; ++i) {
                    float4 t = *(const float4*)&s[(rt*4+i)*N_ + mgs + mi];
                    ev[i][0]=t.x; ev[i][1]=t.y; ev[i][2]=t.z; ev[i][3]=t.w;
                }
                #pragma unroll
                for (int u = 0; u < 4; ++u) {
                    float4 t = *(const float4*)&vt[(mloc+mi+u)*64 + ht*4];
                    vv[u][0]=t.x; vv[u][1]=t.y; vv[u][2]=t.z; vv[u][3]=t.w;
                }
                #pragma unroll
                for (int i = 0; i < 4; ++i)
                    #pragma unroll
                    for (int j = 0; j < 4; ++j)
                        acc[i][j] += ev[i][0]*vv[0][j] + ev[i][1]*vv[1][j]
                                   + ev[i][2]*vv[2][j] + ev[i][3]*vv[3][j];
            }
            __syncthreads();
        }
        // reduce the 4 m-quarters through smem
        float* sc = kt;                    // [4][16][64]
        #pragma unroll
        for (int i = 0; i < 4; ++i) {
            float4 r;
            r.x = acc[i][0]; r.y = acc[i][1]; r.z = acc[i][2]; r.w = acc[i][3];
            *(float4*)&sc[(mt*16 + rt*4 + i)*64 + ht*4] = r;
        }
        __syncthreads();
        {
            int r = tid >> 4, h4 = tid & 15;
            float4 a = *(const float4*)&sc[(0*16 + r)*64 + h4*4];
            #pragma unroll
            for (int g = 1; g < 4; ++g) {
                float4 t = *(const float4*)&sc[(g*16 + r)*64 + h4*4];
                a.x += t.x; a.y += t.y; a.z += t.z; a.w += t.w;
            }
            float inv = __fdividef(1.f, rowsum[r] + 1e-5f);
            a.x *= inv; a.y *= inv; a.z *= inv; a.w *= inv;
            int grow = r0 + r;
            if (r < TM && grow < N_)
                *(float4*)&out[((size_t)b*N_ + grow)*H_ + h4*4] = a;
        }
    }
}

// ---------------------------------------------------------------------------
extern "C" void kernel_launch(void* const* d_in, const int* in_sizes, int n_in,
                              void* d_out, int out_size)
{
    const float* x  = (const float*)d_in[0];
    const float* Wq = (const float*)d_in[1];
    const float* bq = (const float*)d_in[2];
    const float* Wk = (const float*)d_in[3];
    const float* bk = (const float*)d_in[4];
    const float* Wv = (const float*)d_in[5];
    const float* bv = (const float*)d_in[6];
    const float* cw = (const float*)d_in[7];
    const float* cb = (const float*)d_in[8];
    float* out = (float*)d_out;

    qkv_kernel_75625784<<<dim3(512, 3), 256>>>(x, Wq, bq, Wk, bk, Wv, bv);

    const size_t smem_bytes =
        (size_t)(SROWS*N_ + 64*KTS + SROWS*H_ + 16 + 10) * sizeof(float);
    cudaFuncSetAttribute(attn_kernel_75625784,
                         cudaFuncAttributeMaxDynamicSharedMemorySize,
                         (int)smem_bytes);
    attn_kernel_75625784<<<dim3(NTILES, B_), 256, smem_bytes>>>(cw, cb, out);
}

// round 4
// speedup vs baseline: 1.0012x; 1.0012x over previous
#include <cuda_runtime.h>

#define B_ 16
#define N_ 2048
#define D_ 256
#define H_ 64
#define TM 14          // output rows per tile
#define SROWS 16       // TM + 2 halo rows
#define NTILES 147     // ceil(N_/TM)
#define KTS 260        // padded stride for transposed k chunk (multiple of 4, 260%32==4)
#define SCALE 0.125f   // H^-0.5

__device__ float g_q[B_*N_*H_];
__device__ float g_k[B_*N_*H_];
__device__ float g_v[B_*N_*H_];

// ---------------------------------------------------------------------------
// Kernel 1: QKV projection.  out[b,n,h] = x[b,n,:] @ W[:,h] + bias[h]
// grid = (512, 3): 64 rows per CTA, blockIdx.y selects {q,k,v}
// ---------------------------------------------------------------------------
__global__ __launch_bounds__(256) void qkv_kernel_75625784(
    const float* __restrict__ x,
    const float* __restrict__ Wq, const float* __restrict__ bq,
    const float* __restrict__ Wk, const float* __restrict__ bk,
    const float* __restrict__ Wv, const float* __restrict__ bv)
{
    __shared__ float xs[64*64];
    __shared__ float ws[64*64];
    const int mat = blockIdx.y;
    const float* W    = (mat==0) ? Wq : (mat==1 ? Wk : Wv);
    const float* bias = (mat==0) ? bq : (mat==1 ? bk : bv);
    float* outg       = (mat==0) ? g_q : (mat==1 ? g_k : g_v);
    const int row0 = blockIdx.x * 64;
    const int tid = threadIdx.x;
    const int rt = tid >> 4;    // 0..15  (rows rt*4..rt*4+3)
    const int ht = tid & 15;    // 0..15  (cols ht*4..ht*4+3)

    float acc[4][4];
    #pragma unroll
    for (int i = 0; i < 4; ++i)
        #pragma unroll
        for (int j = 0; j < 4; ++j) acc[i][j] = 0.f;

    for (int dc = 0; dc < D_; dc += 64) {
        #pragma unroll
        for (int it = 0; it < 4; ++it) {
            int fi = it*256 + tid;
            int r = fi >> 4, c4 = fi & 15;
            *(float4*)&xs[r*64 + c4*4] =
                *(const float4*)&x[(size_t)(row0 + r)*D_ + dc + c4*4];
            *(float4*)&ws[r*64 + c4*4] =
                *(const float4*)&W[(size_t)(dc + r)*H_ + c4*4];
        }
        __syncthreads();
        #pragma unroll
        for (int d4 = 0; d4 < 16; ++d4) {
            float av[4][4], bv4[4][4];
            #pragma unroll
            for (int i = 0; i < 4; ++i) {
                float4 t = *(const float4*)&xs[(rt*4+i)*64 + d4*4];
                av[i][0]=t.x; av[i][1]=t.y; av[i][2]=t.z; av[i][3]=t.w;
            }
            #pragma unroll
            for (int u = 0; u < 4; ++u) {
                float4 t = *(const float4*)&ws[(d4*4+u)*64 + ht*4];
                bv4[u][0]=t.x; bv4[u][1]=t.y; bv4[u][2]=t.z; bv4[u][3]=t.w;
            }
            #pragma unroll
            for (int i = 0; i < 4; ++i)
                #pragma unroll
                for (int j = 0; j < 4; ++j)
                    acc[i][j] += av[i][0]*bv4[0][j] + av[i][1]*bv4[1][j]
                               + av[i][2]*bv4[2][j] + av[i][3]*bv4[3][j];
        }
        __syncthreads();
    }
    float4 bb = *(const float4*)&bias[ht*4];
    #pragma unroll
    for (int i = 0; i < 4; ++i) {
        float4 r;
        r.x = acc[i][0] + bb.x; r.y = acc[i][1] + bb.y;
        r.z = acc[i][2] + bb.z; r.w = acc[i][3] + bb.w;
        *(float4*)&outg[(size_t)(row0 + rt*4 + i)*H_ + ht*4] = r;
    }
}

// ---------------------------------------------------------------------------
// Kernel 2: fused  A = scale*(q k^T); conv3x3+sigmoid; relu(A - .); expm1;
//           zero-softmax-normalized e @ v.
// grid = (NTILES, B_), 256 threads, ~202 KB dynamic smem (1 CTA/SM)
// ---------------------------------------------------------------------------
__global__ __launch_bounds__(256, 1) void attn_kernel_75625784(
    const float* __restrict__ conv_w, const float* __restrict__ conv_b,
    float* __restrict__ out)
{
    extern __shared__ float smem[];
    float* s      = smem;                      // [SROWS][N_]      131072 B
    float* kt     = s + SROWS*N_;              // [64][KTS]         66560 B (reused: vt[128][64], scratch[4][16][64])
    float* qt     = kt + 64*KTS;               // [SROWS][H_]        4096 B
    float* rowsum = qt + SROWS*H_;             // [16]
    float* cw     = rowsum + 16;               // [10]

    const int b   = blockIdx.y;
    const int r0  = blockIdx.x * TM;
    const int tid = threadIdx.x;

    if (tid < 16) rowsum[tid] = 0.f;
    if (tid < 9)  cw[tid] = conv_w[tid];
    if (tid == 9) cw[9]   = conv_b[0];
    // q tile (16 rows incl. halo; out-of-range rows zeroed => s row == 0, matching conv zero-pad)
    {
        int i = tid >> 4, h4 = tid & 15;
        int g = r0 - 1 + i;
        float4 qv = make_float4(0.f, 0.f, 0.f, 0.f);
        if (g >= 0 && g < N_)
            qv = *(const float4*)&g_q[((size_t)b*N_ + g)*H_ + h4*4];
        *(float4*)&qt[i*H_ + h4*4] = qv;
    }
    __syncthreads();

    // ---------------- Phase 1: s[i][m] = scale * q_i . k_m ----------------
    {
        const int rt = tid >> 6;          // 0..3  -> rows rt*4..rt*4+3
        const int ct = tid & 63;          // 0..63 -> cols ct*4..ct*4+3 within chunk
        const int hh = tid & 63;          // transpose-loader role
        const int mg = tid >> 6;

        for (int mb = 0; mb < N_; mb += 256) {
            const float* kbase = &g_k[((size_t)b*N_ + mb)*H_];
            #pragma unroll
            for (int it = 0; it < 16; ++it) {
                int m0 = mg*4 + it*16;
                float4 v;
                v.x = kbase[(m0+0)*H_ + hh];
                v.y = kbase[(m0+1)*H_ + hh];
                v.z = kbase[(m0+2)*H_ + hh];
                v.w = kbase[(m0+3)*H_ + hh];
                *(float4*)&kt[hh*KTS + m0] = v;     // conflict-free (stride 260)
            }
            __syncthreads();

            float acc[4][4];
            #pragma unroll
            for (int i = 0; i < 4; ++i)
                #pragma unroll
                for (int j = 0; j < 4; ++j) acc[i][j] = 0.f;

            #pragma unroll
            for (int k4 = 0; k4 < 16; ++k4) {
                float av[4][4], bv4[4][4];
                #pragma unroll
                for (int i = 0; i < 4; ++i) {
                    float4 t = *(const float4*)&qt[(rt*4+i)*H_ + k4*4];
                    av[i][0]=t.x; av[i][1]=t.y; av[i][2]=t.z; av[i][3]=t.w;
                }
                #pragma unroll
                for (int u = 0; u < 4; ++u) {
                    float4 t = *(const float4*)&kt[(k4*4+u)*KTS + ct*4];
                    bv4[u][0]=t.x; bv4[u][1]=t.y; bv4[u][2]=t.z; bv4[u][3]=t.w;
                }
                #pragma unroll
                for (int i = 0; i < 4; ++i)
                    #pragma unroll
                    for (int j = 0; j < 4; ++j)
                        acc[i][j] += av[i][0]*bv4[0][j] + av[i][1]*bv4[1][j]
                                   + av[i][2]*bv4[2][j] + av[i][3]*bv4[3][j];
            }
            #pragma unroll
            for (int i = 0; i < 4; ++i) {
                float4 r;
                r.x = acc[i][0]*SCALE; r.y = acc[i][1]*SCALE;
                r.z = acc[i][2]*SCALE; r.w = acc[i][3]*SCALE;
                *(float4*)&s[(rt*4+i)*N_ + mb + ct*4] = r;
            }
            __syncthreads();
        }
    }

    // ------- Phase 2: conv3x3 + sigmoid + relu + (exp-1), in-place shift -------
    {
        const float w0=cw[0],w1=cw[1],w2=cw[2],w3=cw[3],w4=cw[4],
                    w5=cw[5],w6=cw[6],w7=cw[7],w8=cw[8],cb=cw[9];
        const int lane = tid & 31;
        for (int i = 1; i <= TM; ++i) {
            float ev[8]; float psum = 0.f;
            const float* sm1 = &s[(i-1)*N_];
            const float* s0  = &s[ i   *N_];
            const float* sp1 = &s[(i+1)*N_];
            #pragma unroll
            for (int j = 0; j < 8; ++j) {
                int m = tid + j*256;
                float l0 = (m>0)     ? sm1[m-1] : 0.f;
                float l1 = sm1[m];
                float l2 = (m<N_-1)  ? sm1[m+1] : 0.f;
                float c0 = (m>0)     ? s0[m-1]  : 0.f;
                float c1 = s0[m];
                float c2 = (m<N_-1)  ? s0[m+1]  : 0.f;
                float d0 = (m>0)     ? sp1[m-1] : 0.f;
                float d1 = sp1[m];
                float d2 = (m<N_-1)  ? sp1[m+1] : 0.f;
                float conv = cb + w0*l0 + w1*l1 + w2*l2
                                + w3*c0 + w4*c1 + w5*c2
                                + w6*d0 + w7*d1 + w8*d2;
                float sig = __fdividef(1.f, 1.f + __expf(-conv));
                float a = c1 - sig;
                a = fmaxf(a, 0.f);
                float e = __expf(a) - 1.f;
                ev[j] = e; psum += e;
            }
            __syncthreads();                    // all reads of row i-1 done
            #pragma unroll
            for (int j = 0; j < 8; ++j) s[(i-1)*N_ + tid + j*256] = ev[j];
            #pragma unroll
            for (int off = 16; off > 0; off >>= 1)
                psum += __shfl_down_sync(0xffffffffu, psum, off);
            if (lane == 0) atomicAdd(&rowsum[i-1], psum);
            __syncthreads();
        }
        // rows TM..SROWS-1 are stale A_dense halo -> zero so phase 3 tiles cleanly
        for (int idx = tid; idx < 2*N_; idx += 256) s[TM*N_ + idx] = 0.f;
        __syncthreads();
    }

    // ---------------- Phase 3: out = (e @ v) / (rowsum + eps) ----------------
    {
        const int mt = tid >> 6;          // m-quarter 0..3
        const int rt = (tid >> 4) & 3;    // rows rt*4..rt*4+3
        const int ht = tid & 15;          // h cols ht*4..ht*4+3
        float acc[4][4];
        #pragma unroll
        for (int i = 0; i < 4; ++i)
            #pragma unroll
            for (int j = 0; j < 4; ++j) acc[i][j] = 0.f;

        float* vt = kt;                   // reuse as [128][64]
        for (int stp = 0; stp < 16; ++stp) {
            #pragma unroll
            for (int it = 0; it < 8; ++it) {
                int fi = it*256 + tid;           // 0..2047 float4 slots
                int g = fi >> 9, rem = fi & 511;
                int mi = rem >> 4, h4 = rem & 15;
                int m = g*512 + stp*32 + mi;
                *(float4*)&vt[(g*32+mi)*64 + h4*4] =
                    *(const float4*)&g_v[((size_t)b*N_ + m)*H_ + h4*4];
            }
            __syncthreads();
            const int mloc = mt*32;
            const int mgs  = mt*512 + stp*32;
            #pragma unroll
            for (int mi = 0; mi < 32; mi += 4) {
                float ev[4][4], vv[4][4];
                #pragma unroll
                for (int i = 0; i < 4; ++i) {
                    float4 t = *(const float4*)&s[(rt*4+i)*N_ + mgs + mi];
                    ev[i][0]=t.x; ev[i][1]=t.y; ev[i][2]=t.z; ev[i][3]=t.w;
                }
                #pragma unroll
                for (int u = 0; u < 4; ++u) {
                    float4 t = *(const float4*)&vt[(mloc+mi+u)*64 + ht*4];
                    vv[u][0]=t.x; vv[u][1]=t.y; vv[u][2]=t.z; vv[u][3]=t.w;
                }
                #pragma unroll
                for (int i = 0; i < 4; ++i)
                    #pragma unroll
                    for (int j = 0; j < 4; ++j)
                        acc[i][j] += ev[i][0]*vv[0][j] + ev[i][1]*vv[1][j]
                                   + ev[i][2]*vv[2][j] + ev[i][3]*vv[3][j];
            }
            __syncthreads();
        }
        // reduce the 4 m-quarters through smem
        float* sc = kt;                    // [4][16][64]
        #pragma unroll
        for (int i = 0; i < 4; ++i) {
            float4 r;
            r.x = acc[i][0]; r.y = acc[i][1]; r.z = acc[i][2]; r.w = acc[i][3];
            *(float4*)&sc[(mt*16 + rt*4 + i)*64 + ht*4] = r;
        }
        __syncthreads();
        {
            int r = tid >> 4, h4 = tid & 15;
            float4 a = *(const float4*)&sc[(0*16 + r)*64 + h4*4];
            #pragma unroll
            for (int g = 1; g < 4; ++g) {
                float4 t = *(const float4*)&sc[(g*16 + r)*64 + h4*4];
                a.x += t.x; a.y += t.y; a.z += t.z; a.w += t.w;
            }
            float inv = __fdividef(1.f, rowsum[r] + 1e-5f);
            a.x *= inv; a.y *= inv; a.z *= inv; a.w *= inv;
            int grow = r0 + r;
            if (r < TM && grow < N_)
                *(float4*)&out[((size_t)b*N_ + grow)*H_ + h4*4] = a;
        }
    }
}

// ---------------------------------------------------------------------------
extern "C" void kernel_launch(void* const* d_in, const int* in_sizes, int n_in,
                              void* d_out, int out_size)
{
    const float* x  = (const float*)d_in[0];
    const float* Wq = (const float*)d_in[1];
    const float* bq = (const float*)d_in[2];
    const float* Wk = (const float*)d_in[3];
    const float* bk = (const float*)d_in[4];
    const float* Wv = (const float*)d_in[5];
    const float* bv = (const float*)d_in[6];
    const float* cw = (const float*)d_in[7];
    const float* cb = (const float*)d_in[8];
    float* out = (float*)d_out;

    qkv_kernel_75625784<<<dim3(512, 3), 256>>>(x, Wq, bq, Wk, bk, Wv, bv);

    const size_t smem_bytes =
        (size_t)(SROWS*N_ + 64*KTS + SROWS*H_ + 16 + 10) * sizeof(float);
    cudaFuncSetAttribute(attn_kernel_75625784,
                         cudaFuncAttributeMaxDynamicSharedMemorySize,
                         (int)smem_bytes);
    attn_kernel_75625784<<<dim3(NTILES, B_), 256, smem_bytes>>>(cw, cb, out);
}